// round 4
// baseline (speedup 1.0000x reference)
#include <cuda_runtime.h>
#include <cuda_bf16.h>

// ---------------------------------------------------------------------------
// Problem constants
// ---------------------------------------------------------------------------
#define BATCH 8
#define CHANNELS 1024
#define HW 2304           // 48*48
#define POOL_P 576        // 24*24
#define POS_TOTAL (BATCH*POOL_P*POOL_P)   // 2,654,208
#define EPS_L2 1e-6f
#define EPS_MM 1e-5f

typedef unsigned long long u64;

// ---------------------------------------------------------------------------
// Scratch (device globals; no allocation allowed)
// ---------------------------------------------------------------------------
// A in MMA-fragment layout: [b][rowblk 18][ktile 128][mtile 8][lane 32][4]
// B in MMA-fragment layout: [b][colblk 18][ktile 128][ntile 16][lane 32][2]
__device__ float g_A[BATCH * HW * CHANNELS];
__device__ float g_B[BATCH * HW * CHANNELS];
__device__ float g_invnA[BATCH * HW];
__device__ float g_invnB[BATCH * HW];
__device__ float g_cpool[POS_TOTAL];          // pooled corr / conv3 out (reused)
__device__ float g_x1[BATCH * 10 * POOL_P * POOL_P];
__device__ float g_x2[BATCH * 10 * POOL_P * POOL_P];
__device__ float g_amax[BATCH * POOL_P];      // stores reciprocals 1/(max+eps)
__device__ float g_bmax[BATCH * POOL_P];

// ---------------------------------------------------------------------------
// Helpers
// ---------------------------------------------------------------------------
__device__ __forceinline__ unsigned smem_u32(const void* p) {
    return (unsigned)__cvta_generic_to_shared(p);
}
__device__ __forceinline__ u64 pack2(float a, float b) {
    u64 r; asm("mov.b64 %0, {%1, %2};" : "=l"(r) : "f"(a), "f"(b)); return r;
}
__device__ __forceinline__ void fma2(u64& d, u64 a, u64 b) {
    asm("fma.rn.f32x2 %0, %1, %2, %0;" : "+l"(d) : "l"(a), "l"(b));
}
__device__ __forceinline__ float2 unpack2(u64 v) {
    float2 r; asm("mov.b64 {%0, %1}, %2;" : "=f"(r.x), "=f"(r.y) : "l"(v)); return r;
}
__device__ __forceinline__ float tf32r(float v) {
    unsigned t; asm("cvt.rna.tf32.f32 %0, %1;" : "=r"(t) : "f"(v));
    return __uint_as_float(t);
}

// ---------------------------------------------------------------------------
// 1) inverse L2 norm per (b, hw) for both feature tensors
// ---------------------------------------------------------------------------
__global__ void invnorm_kernel(const float* __restrict__ A, const float* __restrict__ B) {
    int t = blockIdx.x * blockDim.x + threadIdx.x;
    if (t >= 2 * BATCH * HW) return;
    const float* f = (t < BATCH * HW) ? A : B;
    float* o = (t < BATCH * HW) ? g_invnA : g_invnB;
    int idx = t % (BATCH * HW);
    int b = idx / HW, hw = idx % HW;
    const float* p = f + (size_t)b * CHANNELS * HW + hw;
    float s = 0.f;
#pragma unroll 8
    for (int c = 0; c < CHANNELS; ++c) {
        float v = p[(size_t)c * HW];
        s = fmaf(v, v, s);
    }
    o[idx] = rsqrtf(s + EPS_L2);
}

// ---------------------------------------------------------------------------
// 2) transpose + normalize + tf32-round, writing MMA-fragment-ordered layout.
// ---------------------------------------------------------------------------
template <int MODE>
__global__ __launch_bounds__(256) void transnorm_kernel(
    const float* __restrict__ f, const float* __restrict__ invn,
    float* __restrict__ out) {
    __shared__ float sm[32][33];
    int b = blockIdx.z;
    int pb = blockIdx.x;        // block of 32 permuted positions (0..71)
    int c0 = blockIdx.y * 32;   // channel block
    int g0 = pb * 8;            // first 2x2 pool group
    int hbase = (g0 / 24) * 2;
    int wbase = (g0 % 24) * 2;
    int tid = threadIdx.x;

    for (int idx = tid; idx < 1024; idx += 256) {
        int ci = idx >> 5, pos = idx & 31;
        int hh = pos >> 4, ww = pos & 15;
        int hw = (hbase + hh) * 48 + wbase + ww;
        float v = f[((size_t)b * CHANNELS + c0 + ci) * HW + hw] * invn[b * HW + hw];
        int p_in = ((ww >> 1) << 2) | (hh << 1) | (ww & 1);   // p' within block
        sm[p_in][ci] = tf32r(v);
    }
    __syncthreads();

    int p0 = pb * 32;
    if (MODE == 0) {
        int mt = tid >> 7, kt = (tid >> 5) & 3, lane = tid & 31;
        int rowin = lane >> 2, colin = lane & 3;
        float4 v;
        v.x = sm[mt * 16 + rowin][kt * 8 + colin];
        v.y = sm[mt * 16 + rowin + 8][kt * 8 + colin];
        v.z = sm[mt * 16 + rowin][kt * 8 + colin + 4];
        v.w = sm[mt * 16 + rowin + 8][kt * 8 + colin + 4];
        int rowblk = p0 >> 7;
        int mtile_g = ((p0 >> 4) & 7) + mt;
        int ktile_g = (c0 >> 3) + kt;
        size_t off = ((((size_t)b * 18 + rowblk) * 128 + ktile_g) * 8 + mtile_g) * 128
                     + lane * 4;
        *(float4*)(out + off) = v;
    } else {
        int colblk = p0 >> 7;
#pragma unroll
        for (int i = 0; i < 2; ++i) {
            int id = tid + i * 256;
            int nt = id >> 7, kt = (id >> 5) & 3, lane = id & 31;
            int rowin = lane >> 2, colin = lane & 3;
            float2 v;
            v.x = sm[nt * 8 + rowin][kt * 8 + colin];
            v.y = sm[nt * 8 + rowin][kt * 8 + colin + 4];
            int ntile_g = ((p0 >> 3) & 15) + nt;
            int ktile_g = (c0 >> 3) + kt;
            size_t off = ((((size_t)b * 18 + colblk) * 128 + ktile_g) * 16 + ntile_g) * 64
                         + lane * 2;
            *(float2*)(out + off) = v;
        }
    }
}

// ---------------------------------------------------------------------------
// 3) batched TF32 GEMM (mma.sync.m16n8k8) + fused 4x4 max-pool + relu/L2.
// ---------------------------------------------------------------------------
#define STAGE_FLOATS 4096   // 4 ktiles * 1024 floats

__global__ __launch_bounds__(256) void gemm_pool_kernel(
    const float* __restrict__ A, const float* __restrict__ B,
    float* __restrict__ out) {
    extern __shared__ char smem_raw[];
    float* As = (float*)smem_raw;            // [2][4096]
    float* Bs = As + 2 * STAGE_FLOATS;       // [2][4096]
    float* Cs = (float*)smem_raw;            // reused: [128][132]

    int b = blockIdx.z;
    const float* Ag = A + (size_t)b * HW * CHANNELS + (size_t)blockIdx.y * 128 * 1024;
    const float* Bg = B + (size_t)b * HW * CHANNELS + (size_t)blockIdx.x * 128 * 1024;

    int tid = threadIdx.x, lane = tid & 31, wid = tid >> 5;
    int wm = wid >> 2, wn = wid & 3;   // 2 x 4 warp grid, warp tile 64x32

    float acc[4][4][4];
#pragma unroll
    for (int i = 0; i < 4; ++i)
#pragma unroll
        for (int j = 0; j < 4; ++j)
#pragma unroll
            for (int k = 0; k < 4; ++k) acc[i][j][k] = 0.f;

    auto load_stage = [&](int s, int kt) {
        const float* ga = Ag + (size_t)kt * STAGE_FLOATS;
        const float* gb = Bg + (size_t)kt * STAGE_FLOATS;
#pragma unroll
        for (int i = 0; i < 4; ++i) {
            int idx = tid + i * 256;    // float4 index 0..1023
            unsigned sa = smem_u32(As + s * STAGE_FLOATS + idx * 4);
            asm volatile("cp.async.cg.shared.global [%0], [%1], 16;\n" :: "r"(sa), "l"(ga + idx * 4));
            unsigned sb = smem_u32(Bs + s * STAGE_FLOATS + idx * 4);
            asm volatile("cp.async.cg.shared.global [%0], [%1], 16;\n" :: "r"(sb), "l"(gb + idx * 4));
        }
        asm volatile("cp.async.commit_group;\n");
    };

    load_stage(0, 0);
    const int KT = CHANNELS / 32;   // 32 stages
    for (int kt = 0; kt < KT; ++kt) {
        asm volatile("cp.async.wait_group 0;\n");
        __syncthreads();            // data ready + previous buffer fully consumed
        int cur = kt & 1;
        if (kt + 1 < KT) load_stage(cur ^ 1, kt + 1);
        const float* Ab = As + cur * STAGE_FLOATS;
        const float* Bb = Bs + cur * STAGE_FLOATS;
#pragma unroll
        for (int kk = 0; kk < 4; ++kk) {
            uint2 bf[4];
#pragma unroll
            for (int ni = 0; ni < 4; ++ni)
                bf[ni] = *(const uint2*)(Bb + ((kk * 16 + wn * 4 + ni) * 32 + lane) * 2);
#pragma unroll
            for (int mi = 0; mi < 4; ++mi) {
                uint4 af = *(const uint4*)(Ab + ((kk * 8 + wm * 4 + mi) * 32 + lane) * 4);
#pragma unroll
                for (int ni = 0; ni < 4; ++ni) {
                    asm volatile(
                        "mma.sync.aligned.m16n8k8.row.col.f32.tf32.tf32.f32 "
                        "{%0,%1,%2,%3}, {%4,%5,%6,%7}, {%8,%9}, {%0,%1,%2,%3};\n"
                        : "+f"(acc[mi][ni][0]), "+f"(acc[mi][ni][1]),
                          "+f"(acc[mi][ni][2]), "+f"(acc[mi][ni][3])
                        : "r"(af.x), "r"(af.y), "r"(af.z), "r"(af.w),
                          "r"(bf[ni].x), "r"(bf[ni].y));
                }
            }
        }
    }
    __syncthreads();   // all warps done with operand smem; reuse as Cs

#pragma unroll
    for (int mi = 0; mi < 4; ++mi) {
#pragma unroll
        for (int ni = 0; ni < 4; ++ni) {
            int r0 = wm * 64 + mi * 16 + (lane >> 2);
            int c0 = wn * 32 + ni * 8 + (lane & 3) * 2;
            Cs[r0 * 132 + c0]           = acc[mi][ni][0];
            Cs[r0 * 132 + c0 + 1]       = acc[mi][ni][1];
            Cs[(r0 + 8) * 132 + c0]     = acc[mi][ni][2];
            Cs[(r0 + 8) * 132 + c0 + 1] = acc[mi][ni][3];
        }
    }
    __syncthreads();

#pragma unroll
    for (int o = 0; o < 4; ++o) {
        int idx = tid * 4 + o;
        int pp = idx >> 5, qq = idx & 31;
        float m = -1e30f;
#pragma unroll
        for (int i = 0; i < 4; ++i)
#pragma unroll
            for (int j = 0; j < 4; ++j)
                m = fmaxf(m, Cs[(pp * 4 + i) * 132 + qq * 4 + j]);
        m = fmaxf(m, 0.f);
        float v = m * rsqrtf(m * m + EPS_L2);
        out[((size_t)b * POOL_P + blockIdx.y * 32 + pp) * POOL_P + blockIdx.x * 32 + qq] = v;
    }
}

// ---------------------------------------------------------------------------
// 4) row / col maxes -> stored as reciprocals 1/(max+eps)
// ---------------------------------------------------------------------------
__global__ void rowmax_kernel(const float* __restrict__ X, float* __restrict__ amax) {
    int row = blockIdx.x, b = blockIdx.y;
    const float* p = X + ((size_t)b * POOL_P + row) * POOL_P;
    float m = 0.f;
    for (int q = threadIdx.x; q < POOL_P; q += 64) m = fmaxf(m, p[q]);
    __shared__ float red[64];
    red[threadIdx.x] = m;
    __syncthreads();
    if (threadIdx.x < 32) {
        m = fmaxf(red[threadIdx.x], red[threadIdx.x + 32]);
#pragma unroll
        for (int s = 16; s; s >>= 1) m = fmaxf(m, __shfl_down_sync(0xffffffffu, m, s));
        if (threadIdx.x == 0) amax[b * POOL_P + row] = 1.0f / (m + EPS_MM);
    }
}

__global__ void colmax_kernel(const float* __restrict__ X, float* __restrict__ bmax) {
    int q = blockIdx.x * 64 + threadIdx.x;
    int b = blockIdx.y;
    const float* p = X + (size_t)b * POOL_P * POOL_P + q;
    float m = 0.f;
#pragma unroll 8
    for (int r = 0; r < POOL_P; ++r) m = fmaxf(m, p[(size_t)r * POOL_P]);
    bmax[b * POOL_P + q] = 1.0f / (m + EPS_MM);
}

// ---------------------------------------------------------------------------
// 5) mutual matching: out = c * (c*ainv[p]) * (c*binv[q])
// ---------------------------------------------------------------------------
__global__ void mm_kernel(const float* __restrict__ X, const float* __restrict__ am,
                          const float* __restrict__ bm, float* __restrict__ O) {
    int i = blockIdx.x * blockDim.x + threadIdx.x;
    if (i >= POS_TOTAL) return;
    int q = i % POOL_P;
    int pr = (i / POOL_P) % POOL_P;
    int b = i / (POOL_P * POOL_P);
    float c = X[i];
    float r = c * am[b * POOL_P + pr];
    float s = c * bm[b * POOL_P + q];
    O[i] = c * r * s;
}

// ---------------------------------------------------------------------------
// 6) Conv4d 3^4 SAME + bias + relu, FFMA2, v2:
//    - 288 threads = 2 (x3,x4) planes (x2 and x2+1), 144 threads each
//    - each thread: 4 consecutive x4 outputs, all Cout
//    - each warp-uniform weight LDS.64 feeds 4 FFMA2 -> fma-pipe-bound
// ---------------------------------------------------------------------------
template <int CIN, int COUT>
__global__ __launch_bounds__(288) void conv4d_v2_kernel(
    const float* __restrict__ in, const float* __restrict__ w,
    const float* __restrict__ bias, float* __restrict__ out) {
    constexpr int CP2 = (COUT + 1) & ~1;
    constexpr int COP = CP2 / 2;
    constexpr int PLN = CIN * 676;     // haloed 26x26 per channel
    extern __shared__ float sm[];
    float* wsm = sm;                   // [CIN*81][CP2] co-minor
    float* pl = sm + CIN * 81 * CP2;   // [2][CIN][26][26]

    int tid = threadIdx.x;
    int b = blockIdx.z, x1 = blockIdx.y, bx = blockIdx.x;
    int half = tid / 144, u = tid % 144;
    int x3 = u / 6, x4 = (u % 6) * 4;
    int x2 = bx * 2 + half;

    for (int i = tid; i < CIN * 81 * CP2; i += 288) {
        int co = i % CP2;
        int rest = i / CP2;
        int ci = rest / 81, tap = rest % 81;
        wsm[i] = (co < COUT) ? w[(co * CIN + ci) * 81 + tap] : 0.f;
    }

    u64 acc[COP][4];
#pragma unroll
    for (int cp = 0; cp < COP; ++cp)
#pragma unroll
        for (int o = 0; o < 4; ++o) acc[cp][o] = 0ull;

    for (int j1 = 0; j1 < 3; ++j1) {
        int y1 = x1 + j1 - 1;
        bool v1 = (unsigned)y1 < 24u;
        for (int j2 = 0; j2 < 3; ++j2) {
            __syncthreads();
            for (int i = tid; i < 2 * PLN; i += 288) {
                int h = i / PLN, r = i % PLN;
                int ci = r / 676, rem = r % 676, rr = rem / 26, cc = rem % 26;
                int y2 = bx * 2 + h + j2 - 1;
                float v = 0.f;
                if (v1 && (unsigned)y2 < 24u &&
                    (unsigned)(rr - 1) < 24u && (unsigned)(cc - 1) < 24u)
                    v = in[((((size_t)b * CIN + ci) * 24 + y1) * 24 + y2) * POOL_P
                           + (rr - 1) * 24 + (cc - 1)];
                pl[i] = v;
            }
            __syncthreads();

            const float* base = pl + half * PLN;
            for (int ci = 0; ci < CIN; ++ci) {
#pragma unroll
                for (int j3 = 0; j3 < 3; ++j3) {
                    const float* vr = base + ci * 676 + (x3 + j3) * 26 + x4;
                    u64 vd[6];
#pragma unroll
                    for (int t = 0; t < 6; ++t) {
                        float vv = vr[t];
                        vd[t] = pack2(vv, vv);
                    }
                    const float* wb = wsm + ((ci * 81 + j1 * 27 + j2 * 9 + j3 * 3) * CP2);
#pragma unroll
                    for (int j4 = 0; j4 < 3; ++j4) {
#pragma unroll
                        for (int cp = 0; cp < COP; ++cp) {
                            u64 wp = *reinterpret_cast<const u64*>(wb + j4 * CP2 + cp * 2);
                            fma2(acc[cp][0], wp, vd[j4]);
                            fma2(acc[cp][1], wp, vd[j4 + 1]);
                            fma2(acc[cp][2], wp, vd[j4 + 2]);
                            fma2(acc[cp][3], wp, vd[j4 + 3]);
                        }
                    }
                }
            }
        }
    }

    // epilogue: 4 consecutive x4 outputs -> float4 stores per channel
    int pos = x3 * 24 + x4;
#pragma unroll
    for (int cp = 0; cp < COP; ++cp) {
        int co0 = 2 * cp, co1 = co0 + 1;
        float2 p0 = unpack2(acc[cp][0]);
        float2 p1 = unpack2(acc[cp][1]);
        float2 p2 = unpack2(acc[cp][2]);
        float2 p3 = unpack2(acc[cp][3]);
        float b0 = bias[co0];
        float4 r0;
        r0.x = fmaxf(p0.x + b0, 0.f);
        r0.y = fmaxf(p1.x + b0, 0.f);
        r0.z = fmaxf(p2.x + b0, 0.f);
        r0.w = fmaxf(p3.x + b0, 0.f);
        size_t off0 = ((((size_t)b * COUT + co0) * 24 + x1) * 24 + x2) * POOL_P + pos;
        *(float4*)(out + off0) = r0;
        if (co1 < COUT) {
            float b1 = bias[co1];
            float4 r1;
            r1.x = fmaxf(p0.y + b1, 0.f);
            r1.y = fmaxf(p1.y + b1, 0.f);
            r1.z = fmaxf(p2.y + b1, 0.f);
            r1.w = fmaxf(p3.y + b1, 0.f);
            size_t off1 = ((((size_t)b * COUT + co1) * 24 + x1) * 24 + x2) * POOL_P + pos;
            *(float4*)(out + off1) = r1;
        }
    }
}

// ---------------------------------------------------------------------------
// Launch
// ---------------------------------------------------------------------------
extern "C" void kernel_launch(void* const* d_in, const int* in_sizes, int n_in,
                              void* d_out, int out_size) {
    const float* fA = (const float*)d_in[0];
    const float* fB = (const float*)d_in[1];
    const float* w1 = (const float*)d_in[2];
    const float* b1 = (const float*)d_in[3];
    const float* w2 = (const float*)d_in[4];
    const float* b2 = (const float*)d_in[5];
    const float* w3 = (const float*)d_in[6];
    const float* b3 = (const float*)d_in[7];
    float* out = (float*)d_out;

    float *gA, *gB, *invA, *invB, *cpool, *x1b, *x2b, *amax, *bmax;
    cudaGetSymbolAddress((void**)&gA, g_A);
    cudaGetSymbolAddress((void**)&gB, g_B);
    cudaGetSymbolAddress((void**)&invA, g_invnA);
    cudaGetSymbolAddress((void**)&invB, g_invnB);
    cudaGetSymbolAddress((void**)&cpool, g_cpool);
    cudaGetSymbolAddress((void**)&x1b, g_x1);
    cudaGetSymbolAddress((void**)&x2b, g_x2);
    cudaGetSymbolAddress((void**)&amax, g_amax);
    cudaGetSymbolAddress((void**)&bmax, g_bmax);

    // smem sizes
    size_t sm1 = (size_t)(1 * 81 * 10 + 2 * 1 * 676) * 4;    //  8.6 KB
    size_t sm2 = (size_t)(10 * 81 * 10 + 2 * 10 * 676) * 4;  // 86.5 KB
    size_t sm3 = (size_t)(10 * 81 * 2 + 2 * 10 * 676) * 4;   // 60.6 KB

    cudaFuncSetAttribute(gemm_pool_kernel, cudaFuncAttributeMaxDynamicSharedMemorySize, 69632);
    cudaFuncSetAttribute(conv4d_v2_kernel<10, 10>, cudaFuncAttributeMaxDynamicSharedMemorySize, (int)sm2);
    cudaFuncSetAttribute(conv4d_v2_kernel<10, 1>, cudaFuncAttributeMaxDynamicSharedMemorySize, (int)sm3);

    // 1) inverse norms
    invnorm_kernel<<<(2 * BATCH * HW) / 256, 256>>>(fA, fB);

    // 2) transpose + normalize + tf32 round into fragment-ordered layouts
    dim3 tgrid(72, 32, BATCH);
    transnorm_kernel<0><<<tgrid, 256>>>(fA, invA, gA);
    transnorm_kernel<1><<<tgrid, 256>>>(fB, invB, gB);

    // 3) TF32 GEMM + pool + relu/L2
    gemm_pool_kernel<<<dim3(18, 18, BATCH), 256, 69632>>>(gA, gB, cpool);

    // 4) mutual matching #1 (in place)
    rowmax_kernel<<<dim3(POOL_P, BATCH), 64>>>(cpool, amax);
    colmax_kernel<<<dim3(POOL_P / 64, BATCH), 64>>>(cpool, bmax);
    mm_kernel<<<(POS_TOTAL + 255) / 256, 256>>>(cpool, amax, bmax, cpool);

    // 5) neighbourhood consensus convs (FFMA2 v2)
    dim3 cgrid(12, 24, BATCH);
    conv4d_v2_kernel<1, 10><<<cgrid, 288, sm1>>>(cpool, w1, b1, x1b);
    conv4d_v2_kernel<10, 10><<<cgrid, 288, sm2>>>(x1b, w2, b2, x2b);
    conv4d_v2_kernel<10, 1><<<cgrid, 288, sm3>>>(x2b, w3, b3, cpool);

    // 6) mutual matching #2 -> output
    rowmax_kernel<<<dim3(POOL_P, BATCH), 64>>>(cpool, amax);
    colmax_kernel<<<dim3(POOL_P / 64, BATCH), 64>>>(cpool, bmax);
    mm_kernel<<<(POS_TOTAL + 255) / 256, 256>>>(cpool, amax, bmax, out);

    (void)in_sizes; (void)n_in; (void)out_size;
}

// round 6
// speedup vs baseline: 1.7952x; 1.7952x over previous
#include <cuda_runtime.h>
#include <cuda_bf16.h>

// ---------------------------------------------------------------------------
// Problem constants
// ---------------------------------------------------------------------------
#define BATCH 8
#define CHANNELS 1024
#define HW 2304           // 48*48
#define POOL_P 576        // 24*24
#define POS_TOTAL (BATCH*POOL_P*POOL_P)   // 2,654,208
#define EPS_L2 1e-6f
#define EPS_MM 1e-5f

typedef unsigned long long u64;

// ---------------------------------------------------------------------------
// Scratch (device globals; no allocation allowed)
// ---------------------------------------------------------------------------
// A in MMA-fragment layout: [b][rowblk 18][ktile 128][mtile 8][lane 32][4]
// B in MMA-fragment layout: [b][colblk 18][ktile 128][ntile 16][lane 32][2]
__device__ float g_A[BATCH * HW * CHANNELS];
__device__ float g_B[BATCH * HW * CHANNELS];
__device__ float g_invnA[BATCH * HW];
__device__ float g_invnB[BATCH * HW];
__device__ float g_cpool[POS_TOTAL];          // pooled corr / conv3 out (reused)
__device__ float g_x1[BATCH * 10 * POOL_P * POOL_P];
__device__ float g_x2[BATCH * 10 * POOL_P * POOL_P];
__device__ float g_amax[BATCH * POOL_P];      // reciprocals 1/(max+eps)
__device__ float g_bmax[BATCH * POOL_P];

// ---------------------------------------------------------------------------
// Helpers
// ---------------------------------------------------------------------------
__device__ __forceinline__ unsigned smem_u32(const void* p) {
    return (unsigned)__cvta_generic_to_shared(p);
}
__device__ __forceinline__ u64 pack2(float a, float b) {
    u64 r; asm("mov.b64 %0, {%1, %2};" : "=l"(r) : "f"(a), "f"(b)); return r;
}
__device__ __forceinline__ void fma2(u64& d, u64 a, u64 b) {
    asm("fma.rn.f32x2 %0, %1, %2, %0;" : "+l"(d) : "l"(a), "l"(b));
}
__device__ __forceinline__ float2 unpack2(u64 v) {
    float2 r; asm("mov.b64 {%0, %1}, %2;" : "=f"(r.x), "=f"(r.y) : "l"(v)); return r;
}
__device__ __forceinline__ float tf32r(float v) {
    unsigned t; asm("cvt.rna.tf32.f32 %0, %1;" : "=r"(t) : "f"(v));
    return __uint_as_float(t);
}

// ---------------------------------------------------------------------------
// 1) inverse L2 norm per (b, hw)
// ---------------------------------------------------------------------------
__global__ void invnorm_kernel(const float* __restrict__ A, const float* __restrict__ B) {
    int t = blockIdx.x * blockDim.x + threadIdx.x;
    if (t >= 2 * BATCH * HW) return;
    const float* f = (t < BATCH * HW) ? A : B;
    float* o = (t < BATCH * HW) ? g_invnA : g_invnB;
    int idx = t % (BATCH * HW);
    int b = idx / HW, hw = idx % HW;
    const float* p = f + (size_t)b * CHANNELS * HW + hw;
    float s = 0.f;
#pragma unroll 8
    for (int c = 0; c < CHANNELS; ++c) {
        float v = p[(size_t)c * HW];
        s = fmaf(v, v, s);
    }
    o[idx] = rsqrtf(s + EPS_L2);
}

// ---------------------------------------------------------------------------
// 2) transpose + normalize + tf32-round into MMA-fragment layout
// ---------------------------------------------------------------------------
template <int MODE>
__global__ __launch_bounds__(256) void transnorm_kernel(
    const float* __restrict__ f, const float* __restrict__ invn,
    float* __restrict__ out) {
    __shared__ float sm[32][33];
    int b = blockIdx.z;
    int pb = blockIdx.x;
    int c0 = blockIdx.y * 32;
    int g0 = pb * 8;
    int hbase = (g0 / 24) * 2;
    int wbase = (g0 % 24) * 2;
    int tid = threadIdx.x;

    for (int idx = tid; idx < 1024; idx += 256) {
        int ci = idx >> 5, pos = idx & 31;
        int hh = pos >> 4, ww = pos & 15;
        int hw = (hbase + hh) * 48 + wbase + ww;
        float v = f[((size_t)b * CHANNELS + c0 + ci) * HW + hw] * invn[b * HW + hw];
        int p_in = ((ww >> 1) << 2) | (hh << 1) | (ww & 1);
        sm[p_in][ci] = tf32r(v);
    }
    __syncthreads();

    int p0 = pb * 32;
    if (MODE == 0) {
        int mt = tid >> 7, kt = (tid >> 5) & 3, lane = tid & 31;
        int rowin = lane >> 2, colin = lane & 3;
        float4 v;
        v.x = sm[mt * 16 + rowin][kt * 8 + colin];
        v.y = sm[mt * 16 + rowin + 8][kt * 8 + colin];
        v.z = sm[mt * 16 + rowin][kt * 8 + colin + 4];
        v.w = sm[mt * 16 + rowin + 8][kt * 8 + colin + 4];
        int rowblk = p0 >> 7;
        int mtile_g = ((p0 >> 4) & 7) + mt;
        int ktile_g = (c0 >> 3) + kt;
        size_t off = ((((size_t)b * 18 + rowblk) * 128 + ktile_g) * 8 + mtile_g) * 128
                     + lane * 4;
        *(float4*)(out + off) = v;
    } else {
        int colblk = p0 >> 7;
#pragma unroll
        for (int i = 0; i < 2; ++i) {
            int id = tid + i * 256;
            int nt = id >> 7, kt = (id >> 5) & 3, lane = id & 31;
            int rowin = lane >> 2, colin = lane & 3;
            float2 v;
            v.x = sm[nt * 8 + rowin][kt * 8 + colin];
            v.y = sm[nt * 8 + rowin][kt * 8 + colin + 4];
            int ntile_g = ((p0 >> 3) & 15) + nt;
            int ktile_g = (c0 >> 3) + kt;
            size_t off = ((((size_t)b * 18 + colblk) * 128 + ktile_g) * 16 + ntile_g) * 64
                         + lane * 2;
            *(float2*)(out + off) = v;
        }
    }
}

// ---------------------------------------------------------------------------
// 3) batched TF32 GEMM + fused 4x4 max-pool + relu/L2  (exact R2 structure)
// ---------------------------------------------------------------------------
#define STAGE_FLOATS 4096   // 4 ktiles * 1024 floats

__global__ __launch_bounds__(256) void gemm_pool_kernel(
    const float* __restrict__ A, const float* __restrict__ B,
    float* __restrict__ out) {
    extern __shared__ char smem_raw[];
    float* As = (float*)smem_raw;            // [2][4096]
    float* Bs = As + 2 * STAGE_FLOATS;       // [2][4096]
    float* Cs = (float*)smem_raw;            // reused: [128][132]

    int b = blockIdx.z;
    const float* Ag = A + (size_t)b * HW * CHANNELS + (size_t)blockIdx.y * 128 * 1024;
    const float* Bg = B + (size_t)b * HW * CHANNELS + (size_t)blockIdx.x * 128 * 1024;

    int tid = threadIdx.x, lane = tid & 31, wid = tid >> 5;
    int wm = wid >> 2, wn = wid & 3;

    float acc[4][4][4];
#pragma unroll
    for (int i = 0; i < 4; ++i)
#pragma unroll
        for (int j = 0; j < 4; ++j)
#pragma unroll
            for (int k = 0; k < 4; ++k) acc[i][j][k] = 0.f;

    auto load_stage = [&](int s, int kt) {
        const float* ga = Ag + (size_t)kt * STAGE_FLOATS;
        const float* gb = Bg + (size_t)kt * STAGE_FLOATS;
#pragma unroll
        for (int i = 0; i < 4; ++i) {
            int idx = tid + i * 256;
            unsigned sa = smem_u32(As + s * STAGE_FLOATS + idx * 4);
            asm volatile("cp.async.cg.shared.global [%0], [%1], 16;\n" :: "r"(sa), "l"(ga + idx * 4));
            unsigned sb = smem_u32(Bs + s * STAGE_FLOATS + idx * 4);
            asm volatile("cp.async.cg.shared.global [%0], [%1], 16;\n" :: "r"(sb), "l"(gb + idx * 4));
        }
        asm volatile("cp.async.commit_group;\n");
    };

    load_stage(0, 0);
    const int KT = CHANNELS / 32;
    for (int kt = 0; kt < KT; ++kt) {
        asm volatile("cp.async.wait_group 0;\n");
        __syncthreads();
        int cur = kt & 1;
        if (kt + 1 < KT) load_stage(cur ^ 1, kt + 1);
        const float* Ab = As + cur * STAGE_FLOATS;
        const float* Bb = Bs + cur * STAGE_FLOATS;
#pragma unroll
        for (int kk = 0; kk < 4; ++kk) {
            uint2 bf[4];
#pragma unroll
            for (int ni = 0; ni < 4; ++ni)
                bf[ni] = *(const uint2*)(Bb + ((kk * 16 + wn * 4 + ni) * 32 + lane) * 2);
#pragma unroll
            for (int mi = 0; mi < 4; ++mi) {
                uint4 af = *(const uint4*)(Ab + ((kk * 8 + wm * 4 + mi) * 32 + lane) * 4);
#pragma unroll
                for (int ni = 0; ni < 4; ++ni) {
                    asm volatile(
                        "mma.sync.aligned.m16n8k8.row.col.f32.tf32.tf32.f32 "
                        "{%0,%1,%2,%3}, {%4,%5,%6,%7}, {%8,%9}, {%0,%1,%2,%3};\n"
                        : "+f"(acc[mi][ni][0]), "+f"(acc[mi][ni][1]),
                          "+f"(acc[mi][ni][2]), "+f"(acc[mi][ni][3])
                        : "r"(af.x), "r"(af.y), "r"(af.z), "r"(af.w),
                          "r"(bf[ni].x), "r"(bf[ni].y));
                }
            }
        }
        __syncthreads();
    }

#pragma unroll
    for (int mi = 0; mi < 4; ++mi) {
#pragma unroll
        for (int ni = 0; ni < 4; ++ni) {
            int r0 = wm * 64 + mi * 16 + (lane >> 2);
            int c0 = wn * 32 + ni * 8 + (lane & 3) * 2;
            Cs[r0 * 132 + c0]           = acc[mi][ni][0];
            Cs[r0 * 132 + c0 + 1]       = acc[mi][ni][1];
            Cs[(r0 + 8) * 132 + c0]     = acc[mi][ni][2];
            Cs[(r0 + 8) * 132 + c0 + 1] = acc[mi][ni][3];
        }
    }
    __syncthreads();

#pragma unroll
    for (int o = 0; o < 4; ++o) {
        int idx = tid * 4 + o;
        int pp = idx >> 5, qq = idx & 31;
        float m = -1e30f;
#pragma unroll
        for (int i = 0; i < 4; ++i)
#pragma unroll
            for (int j = 0; j < 4; ++j)
                m = fmaxf(m, Cs[(pp * 4 + i) * 132 + qq * 4 + j]);
        m = fmaxf(m, 0.f);
        float v = m * rsqrtf(m * m + EPS_L2);
        out[((size_t)b * POOL_P + blockIdx.y * 32 + pp) * POOL_P + blockIdx.x * 32 + qq] = v;
    }
}

// ---------------------------------------------------------------------------
// 4) row / col maxes -> reciprocals 1/(max+eps)
// ---------------------------------------------------------------------------
__global__ void rowmax_kernel(const float* __restrict__ X, float* __restrict__ amax) {
    int row = blockIdx.x, b = blockIdx.y;
    const float* p = X + ((size_t)b * POOL_P + row) * POOL_P;
    float m = 0.f;
    for (int q = threadIdx.x; q < POOL_P; q += 64) m = fmaxf(m, p[q]);
    __shared__ float red[64];
    red[threadIdx.x] = m;
    __syncthreads();
    if (threadIdx.x < 32) {
        m = fmaxf(red[threadIdx.x], red[threadIdx.x + 32]);
#pragma unroll
        for (int s = 16; s; s >>= 1) m = fmaxf(m, __shfl_down_sync(0xffffffffu, m, s));
        if (threadIdx.x == 0) amax[b * POOL_P + row] = 1.0f / (m + EPS_MM);
    }
}

__global__ void colmax_kernel(const float* __restrict__ X, float* __restrict__ bmax) {
    int q = blockIdx.x * 64 + threadIdx.x;
    int b = blockIdx.y;
    const float* p = X + (size_t)b * POOL_P * POOL_P + q;
    float m = 0.f;
#pragma unroll 8
    for (int r = 0; r < POOL_P; ++r) m = fmaxf(m, p[(size_t)r * POOL_P]);
    bmax[b * POOL_P + q] = 1.0f / (m + EPS_MM);
}

// ---------------------------------------------------------------------------
// 5) mutual matching: out = c * (c*ainv[p]) * (c*binv[q])
// ---------------------------------------------------------------------------
__global__ void mm_kernel(const float* __restrict__ X, const float* __restrict__ am,
                          const float* __restrict__ bm, float* __restrict__ O) {
    int i = blockIdx.x * blockDim.x + threadIdx.x;
    if (i >= POS_TOTAL) return;
    int q = i % POOL_P;
    int pr = (i / POOL_P) % POOL_P;
    int b = i / (POOL_P * POOL_P);
    float c = X[i];
    float r = c * am[b * POOL_P + pr];
    float s = c * bm[b * POOL_P + q];
    O[i] = c * r * s;
}

// ---------------------------------------------------------------------------
// 6) Conv4d 3^4 SAME + bias + relu, FFMA2 v3 (fixed alignment):
//    R2 compute structure + double-buffered cp.async plane prefetch.
//    WPAD rounds the weight smem region to 16B so plane buffers are
//    16B-aligned (R5's misaligned-address crash).
// ---------------------------------------------------------------------------
#define RSTR 36              // plane row stride (floats); rows 16B-aligned
#define CSTR (26 * RSTR)     // 936 floats per channel

template <int CIN, int COUT>
__global__ __launch_bounds__(288) void conv4d_v3_kernel(
    const float* __restrict__ in, const float* __restrict__ w,
    const float* __restrict__ bias, float* __restrict__ out) {
    constexpr int CP2 = (COUT + 1) & ~1;
    constexpr int COP = CP2 / 2;
    constexpr int WPAD = (CIN * 81 * CP2 + 3) & ~3;   // 16B-aligned plane base
    constexpr int PLN = CIN * CSTR;
    extern __shared__ float sm[];
    float* wsm = sm;                    // [CIN*81][CP2]
    float* pl = sm + WPAD;              // [2][PLN], 16B aligned

    int tid = threadIdx.x;
    int b = blockIdx.z, x1 = blockIdx.y, x2 = blockIdx.x;
    int x3 = tid / 12, x4 = (tid % 12) * 2;

    // weights -> smem (co-minor)
    for (int i = tid; i < CIN * 81 * CP2; i += 288) {
        int co = i % CP2;
        int rest = i / CP2;
        int ci = rest / 81, tap = rest % 81;
        wsm[i] = (co < COUT) ? w[(co * CIN + ci) * 81 + tap] : 0.f;
    }
    // zero halo rows (0,25) and halo cols ([3],[28]) in both buffers
    for (int i = tid; i < 2 * CIN * 26; i += 288) {
        int bf = i / (CIN * 26), r = i % (CIN * 26);
        int ci = r / 26, rr = r % 26;
        float* rowp = pl + bf * PLN + ci * CSTR + rr * RSTR;
        if (rr == 0 || rr == 25) {
            for (int c = 3; c <= 28; ++c) rowp[c] = 0.f;
        } else {
            rowp[3] = 0.f; rowp[28] = 0.f;
        }
    }

    // prefetch tap g into buffer bf (data rows rr=1..24, cols [4..27])
    auto prefetch = [&](int g, int bf) {
        int y1 = x1 + g / 3 - 1, y2 = x2 + g % 3 - 1;
        bool pv = ((unsigned)y1 < 24u) && ((unsigned)y2 < 24u);
        if (pv) {
            const float* src = in + (((size_t)b * CIN * 24 + y1) * 24 + y2) * POOL_P;
            for (int t = tid; t < CIN * 24; t += 288) {
                int ci = t / 24, rr = 1 + t % 24;
                const float* gs = src + (size_t)ci * (24 * 24 * POOL_P) + (rr - 1) * 24;
                unsigned d = smem_u32(pl + bf * PLN + ci * CSTR + rr * RSTR + 4);
#pragma unroll
                for (int c = 0; c < 6; ++c)
                    asm volatile("cp.async.cg.shared.global [%0], [%1], 16;\n"
                                 :: "r"(d + c * 16), "l"(gs + c * 4));
            }
        } else {
            float4 z = make_float4(0.f, 0.f, 0.f, 0.f);
            for (int t = tid; t < CIN * 24; t += 288) {
                int ci = t / 24, rr = 1 + t % 24;
                float* rowp = pl + bf * PLN + ci * CSTR + rr * RSTR + 4;
#pragma unroll
                for (int c = 0; c < 24; c += 4) *(float4*)(rowp + c) = z;
            }
        }
        asm volatile("cp.async.commit_group;\n");
    };

    u64 acc[COP][2];
#pragma unroll
    for (int cp = 0; cp < COP; ++cp) { acc[cp][0] = 0ull; acc[cp][1] = 0ull; }

    prefetch(0, 0);
    for (int g = 0; g < 9; ++g) {
        if (g + 1 < 9) {
            prefetch(g + 1, (g + 1) & 1);
            asm volatile("cp.async.wait_group 1;\n");
        } else {
            asm volatile("cp.async.wait_group 0;\n");
        }
        __syncthreads();

        const float* base = pl + (g & 1) * PLN;
        int j1 = g / 3, j2 = g % 3;
        for (int ci = 0; ci < CIN; ++ci) {
#pragma unroll
            for (int j3 = 0; j3 < 3; ++j3) {
                const float* vr = base + ci * CSTR + (x3 + j3) * RSTR + 3 + x4;
                float v0 = vr[0], v1 = vr[1], v2 = vr[2], v3 = vr[3];
                u64 vd[4] = {pack2(v0, v0), pack2(v1, v1), pack2(v2, v2), pack2(v3, v3)};
                const float* wb = wsm + (ci * 81 + j1 * 27 + j2 * 9 + j3 * 3) * CP2;
#pragma unroll
                for (int j4 = 0; j4 < 3; ++j4) {
#pragma unroll
                    for (int cp = 0; cp < COP; ++cp) {
                        u64 wp = *reinterpret_cast<const u64*>(wb + j4 * CP2 + cp * 2);
                        fma2(acc[cp][0], wp, vd[j4]);
                        fma2(acc[cp][1], wp, vd[j4 + 1]);
                    }
                }
            }
        }
        __syncthreads();   // buffer (g&1) free for prefetch at g+2
    }

    // epilogue: 2 outputs (x4, x4+1) per channel -> float2 stores
    int pos = x3 * 24 + x4;
#pragma unroll
    for (int cp = 0; cp < COP; ++cp) {
        int co0 = 2 * cp, co1 = co0 + 1;
        float2 p0 = unpack2(acc[cp][0]);   // (co0, co1) at x4
        float2 p1 = unpack2(acc[cp][1]);   // (co0, co1) at x4+1
        float b0 = bias[co0];
        float2 r0 = make_float2(fmaxf(p0.x + b0, 0.f), fmaxf(p1.x + b0, 0.f));
        size_t off0 = ((((size_t)b * COUT + co0) * 24 + x1) * 24 + x2) * POOL_P + pos;
        *(float2*)(out + off0) = r0;
        if (co1 < COUT) {
            float b1 = bias[co1];
            float2 r1 = make_float2(fmaxf(p0.y + b1, 0.f), fmaxf(p1.y + b1, 0.f));
            size_t off1 = ((((size_t)b * COUT + co1) * 24 + x1) * 24 + x2) * POOL_P + pos;
            *(float2*)(out + off1) = r1;
        }
    }
}

// host-side WPAD mirror
static inline size_t conv_smem_bytes(int cin, int cout) {
    int cp2 = (cout + 1) & ~1;
    size_t wpad = ((size_t)cin * 81 * cp2 + 3) & ~(size_t)3;
    return (wpad + 2 * (size_t)cin * CSTR) * 4;
}

// ---------------------------------------------------------------------------
// Launch
// ---------------------------------------------------------------------------
extern "C" void kernel_launch(void* const* d_in, const int* in_sizes, int n_in,
                              void* d_out, int out_size) {
    const float* fA = (const float*)d_in[0];
    const float* fB = (const float*)d_in[1];
    const float* w1 = (const float*)d_in[2];
    const float* b1 = (const float*)d_in[3];
    const float* w2 = (const float*)d_in[4];
    const float* b2 = (const float*)d_in[5];
    const float* w3 = (const float*)d_in[6];
    const float* b3 = (const float*)d_in[7];
    float* out = (float*)d_out;

    float *gA, *gB, *invA, *invB, *cpool, *x1b, *x2b, *amax, *bmax;
    cudaGetSymbolAddress((void**)&gA, g_A);
    cudaGetSymbolAddress((void**)&gB, g_B);
    cudaGetSymbolAddress((void**)&invA, g_invnA);
    cudaGetSymbolAddress((void**)&invB, g_invnB);
    cudaGetSymbolAddress((void**)&cpool, g_cpool);
    cudaGetSymbolAddress((void**)&x1b, g_x1);
    cudaGetSymbolAddress((void**)&x2b, g_x2);
    cudaGetSymbolAddress((void**)&amax, g_amax);
    cudaGetSymbolAddress((void**)&bmax, g_bmax);

    size_t sm1 = conv_smem_bytes(1, 10);    // ~10.7 KB
    size_t sm2 = conv_smem_bytes(10, 10);   // ~107.3 KB
    size_t sm3 = conv_smem_bytes(10, 1);    // ~81.4 KB

    cudaFuncSetAttribute(gemm_pool_kernel, cudaFuncAttributeMaxDynamicSharedMemorySize, 69632);
    cudaFuncSetAttribute(conv4d_v3_kernel<10, 10>, cudaFuncAttributeMaxDynamicSharedMemorySize, (int)sm2);
    cudaFuncSetAttribute(conv4d_v3_kernel<10, 1>, cudaFuncAttributeMaxDynamicSharedMemorySize, (int)sm3);

    // 1) inverse norms
    invnorm_kernel<<<(2 * BATCH * HW) / 256, 256>>>(fA, fB);

    // 2) transpose + normalize + tf32 round into fragment-ordered layouts
    dim3 tgrid(72, 32, BATCH);
    transnorm_kernel<0><<<tgrid, 256>>>(fA, invA, gA);
    transnorm_kernel<1><<<tgrid, 256>>>(fB, invB, gB);

    // 3) TF32 GEMM + pool + relu/L2
    gemm_pool_kernel<<<dim3(18, 18, BATCH), 256, 69632>>>(gA, gB, cpool);

    // 4) mutual matching #1 (in place)
    rowmax_kernel<<<dim3(POOL_P, BATCH), 64>>>(cpool, amax);
    colmax_kernel<<<dim3(POOL_P / 64, BATCH), 64>>>(cpool, bmax);
    mm_kernel<<<(POS_TOTAL + 255) / 256, 256>>>(cpool, amax, bmax, cpool);

    // 5) neighbourhood consensus convs (FFMA2 + async plane prefetch)
    dim3 cgrid(24, 24, BATCH);
    conv4d_v3_kernel<1, 10><<<cgrid, 288, sm1>>>(cpool, w1, b1, x1b);
    conv4d_v3_kernel<10, 10><<<cgrid, 288, sm2>>>(x1b, w2, b2, x2b);
    conv4d_v3_kernel<10, 1><<<cgrid, 288, sm3>>>(x2b, w3, b3, cpool);

    // 6) mutual matching #2 -> output
    rowmax_kernel<<<dim3(POOL_P, BATCH), 64>>>(cpool, amax);
    colmax_kernel<<<dim3(POOL_P / 64, BATCH), 64>>>(cpool, bmax);
    mm_kernel<<<(POS_TOTAL + 255) / 256, 256>>>(cpool, amax, bmax, out);

    (void)in_sizes; (void)n_in; (void)out_size;
}

// round 7
// speedup vs baseline: 2.2629x; 1.2605x over previous
#include <cuda_runtime.h>
#include <cuda_bf16.h>

// ---------------------------------------------------------------------------
// Problem constants
// ---------------------------------------------------------------------------
#define BATCH 8
#define CHANNELS 1024
#define HW 2304           // 48*48
#define POOL_P 576        // 24*24
#define POS_TOTAL (BATCH*POOL_P*POOL_P)   // 2,654,208
#define EPS_L2 1e-6f
#define EPS_MM 1e-5f

typedef unsigned long long u64;

// ---------------------------------------------------------------------------
// Scratch (device globals; no allocation allowed)
// ---------------------------------------------------------------------------
// A in MMA-fragment layout: [b][rowblk 18][ktile 128][mtile 8][lane 32][4]
// B in MMA-fragment layout: [b][colblk 18][ktile 128][ntile 16][lane 32][2]
__device__ float g_A[BATCH * HW * CHANNELS];
__device__ float g_B[BATCH * HW * CHANNELS];
__device__ float g_invnA[BATCH * HW];
__device__ float g_invnB[BATCH * HW];
__device__ float g_cpool[POS_TOTAL];          // pooled corr / conv3 out (reused)
__device__ float g_x1[BATCH * 10 * POOL_P * POOL_P];
__device__ float g_x2[BATCH * 10 * POOL_P * POOL_P];
__device__ float g_amax[BATCH * POOL_P];      // reciprocals 1/(max+eps)
__device__ float g_bmax[BATCH * POOL_P];

// ---------------------------------------------------------------------------
// Helpers
// ---------------------------------------------------------------------------
__device__ __forceinline__ unsigned smem_u32(const void* p) {
    return (unsigned)__cvta_generic_to_shared(p);
}
__device__ __forceinline__ u64 pack2(float a, float b) {
    u64 r; asm("mov.b64 %0, {%1, %2};" : "=l"(r) : "f"(a), "f"(b)); return r;
}
__device__ __forceinline__ void fma2(u64& d, u64 a, u64 b) {
    asm("fma.rn.f32x2 %0, %1, %2, %0;" : "+l"(d) : "l"(a), "l"(b));
}
__device__ __forceinline__ float2 unpack2(u64 v) {
    float2 r; asm("mov.b64 {%0, %1}, %2;" : "=f"(r.x), "=f"(r.y) : "l"(v)); return r;
}
__device__ __forceinline__ float tf32r(float v) {
    unsigned t; asm("cvt.rna.tf32.f32 %0, %1;" : "=r"(t) : "f"(v));
    return __uint_as_float(t);
}

// ---------------------------------------------------------------------------
// 1) inverse L2 norm per (b, hw)
// ---------------------------------------------------------------------------
__global__ void invnorm_kernel(const float* __restrict__ A, const float* __restrict__ B) {
    int t = blockIdx.x * blockDim.x + threadIdx.x;
    if (t >= 2 * BATCH * HW) return;
    const float* f = (t < BATCH * HW) ? A : B;
    float* o = (t < BATCH * HW) ? g_invnA : g_invnB;
    int idx = t % (BATCH * HW);
    int b = idx / HW, hw = idx % HW;
    const float* p = f + (size_t)b * CHANNELS * HW + hw;
    float s = 0.f;
#pragma unroll 8
    for (int c = 0; c < CHANNELS; ++c) {
        float v = p[(size_t)c * HW];
        s = fmaf(v, v, s);
    }
    o[idx] = rsqrtf(s + EPS_L2);
}

// ---------------------------------------------------------------------------
// 2) transpose + normalize + tf32-round into MMA-fragment layout
// ---------------------------------------------------------------------------
template <int MODE>
__global__ __launch_bounds__(256) void transnorm_kernel(
    const float* __restrict__ f, const float* __restrict__ invn,
    float* __restrict__ out) {
    __shared__ float sm[32][33];
    int b = blockIdx.z;
    int pb = blockIdx.x;
    int c0 = blockIdx.y * 32;
    int g0 = pb * 8;
    int hbase = (g0 / 24) * 2;
    int wbase = (g0 % 24) * 2;
    int tid = threadIdx.x;

    for (int idx = tid; idx < 1024; idx += 256) {
        int ci = idx >> 5, pos = idx & 31;
        int hh = pos >> 4, ww = pos & 15;
        int hw = (hbase + hh) * 48 + wbase + ww;
        float v = f[((size_t)b * CHANNELS + c0 + ci) * HW + hw] * invn[b * HW + hw];
        int p_in = ((ww >> 1) << 2) | (hh << 1) | (ww & 1);
        sm[p_in][ci] = tf32r(v);
    }
    __syncthreads();

    int p0 = pb * 32;
    if (MODE == 0) {
        int mt = tid >> 7, kt = (tid >> 5) & 3, lane = tid & 31;
        int rowin = lane >> 2, colin = lane & 3;
        float4 v;
        v.x = sm[mt * 16 + rowin][kt * 8 + colin];
        v.y = sm[mt * 16 + rowin + 8][kt * 8 + colin];
        v.z = sm[mt * 16 + rowin][kt * 8 + colin + 4];
        v.w = sm[mt * 16 + rowin + 8][kt * 8 + colin + 4];
        int rowblk = p0 >> 7;
        int mtile_g = ((p0 >> 4) & 7) + mt;
        int ktile_g = (c0 >> 3) + kt;
        size_t off = ((((size_t)b * 18 + rowblk) * 128 + ktile_g) * 8 + mtile_g) * 128
                     + lane * 4;
        *(float4*)(out + off) = v;
    } else {
        int colblk = p0 >> 7;
#pragma unroll
        for (int i = 0; i < 2; ++i) {
            int id = tid + i * 256;
            int nt = id >> 7, kt = (id >> 5) & 3, lane = id & 31;
            int rowin = lane >> 2, colin = lane & 3;
            float2 v;
            v.x = sm[nt * 8 + rowin][kt * 8 + colin];
            v.y = sm[nt * 8 + rowin][kt * 8 + colin + 4];
            int ntile_g = ((p0 >> 3) & 15) + nt;
            int ktile_g = (c0 >> 3) + kt;
            size_t off = ((((size_t)b * 18 + colblk) * 128 + ktile_g) * 16 + ntile_g) * 64
                         + lane * 2;
            *(float2*)(out + off) = v;
        }
    }
}

// ---------------------------------------------------------------------------
// 3) batched TF32 GEMM + fused 4x4 max-pool + relu/L2.
//    3-stage cp.async pipeline, ONE __syncthreads per k-iteration.
// ---------------------------------------------------------------------------
#define STAGE_FLOATS 4096   // 4 ktiles * 1024 floats

__global__ __launch_bounds__(256) void gemm_pool_kernel(
    const float* __restrict__ A, const float* __restrict__ B,
    float* __restrict__ out) {
    extern __shared__ char smem_raw[];
    float* As = (float*)smem_raw;            // [3][4096]
    float* Bs = As + 3 * STAGE_FLOATS;       // [3][4096]
    float* Cs = (float*)smem_raw;            // reused: [128][132]

    int b = blockIdx.z;
    const float* Ag = A + (size_t)b * HW * CHANNELS + (size_t)blockIdx.y * 128 * 1024;
    const float* Bg = B + (size_t)b * HW * CHANNELS + (size_t)blockIdx.x * 128 * 1024;

    int tid = threadIdx.x, lane = tid & 31, wid = tid >> 5;
    int wm = wid >> 2, wn = wid & 3;

    float acc[4][4][4];
#pragma unroll
    for (int i = 0; i < 4; ++i)
#pragma unroll
        for (int j = 0; j < 4; ++j)
#pragma unroll
            for (int k = 0; k < 4; ++k) acc[i][j][k] = 0.f;

    auto load_stage = [&](int s, int kt) {
        const float* ga = Ag + (size_t)kt * STAGE_FLOATS;
        const float* gb = Bg + (size_t)kt * STAGE_FLOATS;
#pragma unroll
        for (int i = 0; i < 4; ++i) {
            int idx = tid + i * 256;
            unsigned sa = smem_u32(As + s * STAGE_FLOATS + idx * 4);
            asm volatile("cp.async.cg.shared.global [%0], [%1], 16;\n" :: "r"(sa), "l"(ga + idx * 4));
            unsigned sb = smem_u32(Bs + s * STAGE_FLOATS + idx * 4);
            asm volatile("cp.async.cg.shared.global [%0], [%1], 16;\n" :: "r"(sb), "l"(gb + idx * 4));
        }
        asm volatile("cp.async.commit_group;\n");
    };

    const int KT = CHANNELS / 32;   // 32 k-iterations
    load_stage(0, 0);
    load_stage(1, 1);
    for (int kt = 0; kt < KT; ++kt) {
        if (kt + 2 < KT) {
            asm volatile("cp.async.wait_group 1;\n");
        } else {
            asm volatile("cp.async.wait_group 0;\n");
        }
        __syncthreads();
        if (kt + 2 < KT) load_stage((kt + 2) % 3, kt + 2);
        int cur = kt % 3;
        const float* Ab = As + cur * STAGE_FLOATS;
        const float* Bb = Bs + cur * STAGE_FLOATS;
#pragma unroll
        for (int kk = 0; kk < 4; ++kk) {
            uint2 bf[4];
#pragma unroll
            for (int ni = 0; ni < 4; ++ni)
                bf[ni] = *(const uint2*)(Bb + ((kk * 16 + wn * 4 + ni) * 32 + lane) * 2);
#pragma unroll
            for (int mi = 0; mi < 4; ++mi) {
                uint4 af = *(const uint4*)(Ab + ((kk * 8 + wm * 4 + mi) * 32 + lane) * 4);
#pragma unroll
                for (int ni = 0; ni < 4; ++ni) {
                    asm volatile(
                        "mma.sync.aligned.m16n8k8.row.col.f32.tf32.tf32.f32 "
                        "{%0,%1,%2,%3}, {%4,%5,%6,%7}, {%8,%9}, {%0,%1,%2,%3};\n"
                        : "+f"(acc[mi][ni][0]), "+f"(acc[mi][ni][1]),
                          "+f"(acc[mi][ni][2]), "+f"(acc[mi][ni][3])
                        : "r"(af.x), "r"(af.y), "r"(af.z), "r"(af.w),
                          "r"(bf[ni].x), "r"(bf[ni].y));
                }
            }
        }
    }
    __syncthreads();   // operand smem free; reuse as Cs

#pragma unroll
    for (int mi = 0; mi < 4; ++mi) {
#pragma unroll
        for (int ni = 0; ni < 4; ++ni) {
            int r0 = wm * 64 + mi * 16 + (lane >> 2);
            int c0 = wn * 32 + ni * 8 + (lane & 3) * 2;
            Cs[r0 * 132 + c0]           = acc[mi][ni][0];
            Cs[r0 * 132 + c0 + 1]       = acc[mi][ni][1];
            Cs[(r0 + 8) * 132 + c0]     = acc[mi][ni][2];
            Cs[(r0 + 8) * 132 + c0 + 1] = acc[mi][ni][3];
        }
    }
    __syncthreads();

#pragma unroll
    for (int o = 0; o < 4; ++o) {
        int idx = tid * 4 + o;
        int pp = idx >> 5, qq = idx & 31;
        float m = -1e30f;
#pragma unroll
        for (int i = 0; i < 4; ++i)
#pragma unroll
            for (int j = 0; j < 4; ++j)
                m = fmaxf(m, Cs[(pp * 4 + i) * 132 + qq * 4 + j]);
        m = fmaxf(m, 0.f);
        float v = m * rsqrtf(m * m + EPS_L2);
        out[((size_t)b * POOL_P + blockIdx.y * 32 + pp) * POOL_P + blockIdx.x * 32 + qq] = v;
    }
}

// ---------------------------------------------------------------------------
// 4) row / col maxes -> reciprocals 1/(max+eps)
// ---------------------------------------------------------------------------
__global__ void rowmax_kernel(const float* __restrict__ X, float* __restrict__ amax) {
    int row = blockIdx.x, b = blockIdx.y;
    const float* p = X + ((size_t)b * POOL_P + row) * POOL_P;
    float m = 0.f;
    for (int q = threadIdx.x; q < POOL_P; q += 64) m = fmaxf(m, p[q]);
    __shared__ float red[64];
    red[threadIdx.x] = m;
    __syncthreads();
    if (threadIdx.x < 32) {
        m = fmaxf(red[threadIdx.x], red[threadIdx.x + 32]);
#pragma unroll
        for (int s = 16; s; s >>= 1) m = fmaxf(m, __shfl_down_sync(0xffffffffu, m, s));
        if (threadIdx.x == 0) amax[b * POOL_P + row] = 1.0f / (m + EPS_MM);
    }
}

__global__ void colmax_kernel(const float* __restrict__ X, float* __restrict__ bmax) {
    int q = blockIdx.x * 64 + threadIdx.x;
    int b = blockIdx.y;
    const float* p = X + (size_t)b * POOL_P * POOL_P + q;
    float m = 0.f;
#pragma unroll 8
    for (int r = 0; r < POOL_P; ++r) m = fmaxf(m, p[(size_t)r * POOL_P]);
    bmax[b * POOL_P + q] = 1.0f / (m + EPS_MM);
}

// ---------------------------------------------------------------------------
// 5) mutual matching: out = c * (c*ainv[p]) * (c*binv[q])
// ---------------------------------------------------------------------------
__global__ void mm_kernel(const float* __restrict__ X, const float* __restrict__ am,
                          const float* __restrict__ bm, float* __restrict__ O) {
    int i = blockIdx.x * blockDim.x + threadIdx.x;
    if (i >= POS_TOTAL) return;
    int q = i % POOL_P;
    int pr = (i / POOL_P) % POOL_P;
    int b = i / (POOL_P * POOL_P);
    float c = X[i];
    float r = c * am[b * POOL_P + pr];
    float s = c * bm[b * POOL_P + q];
    O[i] = c * r * s;
}

// ---------------------------------------------------------------------------
// 6) Conv4d 3^4 SAME + bias + relu, FFMA2 v4:
//    288 threads = 2 x2-planes x 144; each thread computes a 2x2 (x3,x4)
//    output tile for all Cout. 15 weight LDS.64 now feed 60 FFMA2/block
//    (2x better FFMA2:LDS ratio than v1/v3 -> pipe-bound, not crossbar).
// ---------------------------------------------------------------------------
#define RSTR 36              // plane row stride (floats); rows 16B-aligned
#define CSTR (26 * RSTR)     // 936 floats per channel

template <int CIN, int COUT>
__global__ __launch_bounds__(288) void conv4d_v4_kernel(
    const float* __restrict__ in, const float* __restrict__ w,
    const float* __restrict__ bias, float* __restrict__ out) {
    constexpr int CP2 = (COUT + 1) & ~1;
    constexpr int COP = CP2 / 2;
    constexpr int WPAD = (CIN * 81 * CP2 + 3) & ~3;   // 16B-aligned plane base
    constexpr int PLN = CIN * CSTR;
    extern __shared__ float sm[];
    float* wsm = sm;                    // [CIN*81][CP2]
    float* pl = sm + WPAD;              // [2 halves][PLN]

    int tid = threadIdx.x;
    int b = blockIdx.z, x1 = blockIdx.y, bx = blockIdx.x;
    int half = tid / 144, u = tid % 144;
    int x3 = 2 * (u / 12), x4 = 2 * (u % 12);
    int x2 = bx * 2 + half;

    // weights -> smem (co-minor)
    for (int i = tid; i < CIN * 81 * CP2; i += 288) {
        int co = i % CP2;
        int rest = i / CP2;
        int ci = rest / 81, tap = rest % 81;
        wsm[i] = (co < COUT) ? w[(co * CIN + ci) * 81 + tap] : 0.f;
    }
    // zero halo rows (0,25) and halo cols ([3],[28]) in both halves
    for (int i = tid; i < 2 * CIN * 26; i += 288) {
        int h = i / (CIN * 26), r = i % (CIN * 26);
        int ci = r / 26, rr = r % 26;
        float* rowp = pl + h * PLN + ci * CSTR + rr * RSTR;
        if (rr == 0 || rr == 25) {
            for (int c = 3; c <= 28; ++c) rowp[c] = 0.f;
        } else {
            rowp[3] = 0.f; rowp[28] = 0.f;
        }
    }

    u64 acc[COP][4];
#pragma unroll
    for (int cp = 0; cp < COP; ++cp)
#pragma unroll
        for (int o = 0; o < 4; ++o) acc[cp][o] = 0ull;

    for (int g = 0; g < 9; ++g) {
        int j1 = g / 3, j2 = g % 3;
        int y1 = x1 + j1 - 1;
        bool v1 = (unsigned)y1 < 24u;
        __syncthreads();   // previous tap's compute done before overwrite
        // load both halves' planes (synchronous float4 path)
        for (int t = tid; t < 2 * CIN * 24; t += 288) {
            int h = t / (CIN * 24), r = t % (CIN * 24);
            int ci = r / 24, rr = 1 + r % 24;
            int y2 = bx * 2 + h + j2 - 1;
            float* dst = pl + h * PLN + ci * CSTR + rr * RSTR + 4;
            if (v1 && (unsigned)y2 < 24u) {
                const float* src = in + ((((size_t)b * CIN + ci) * 24 + y1) * 24 + y2) * POOL_P
                                      + (rr - 1) * 24;
#pragma unroll
                for (int c = 0; c < 6; ++c)
                    *(float4*)(dst + c * 4) = *(const float4*)(src + c * 4);
            } else {
                float4 z = make_float4(0.f, 0.f, 0.f, 0.f);
#pragma unroll
                for (int c = 0; c < 6; ++c) *(float4*)(dst + c * 4) = z;
            }
        }
        __syncthreads();

        const float* base = pl + half * PLN;
        for (int ci = 0; ci < CIN; ++ci) {
#pragma unroll
            for (int j3 = 0; j3 < 3; ++j3) {
                const float* r0 = base + ci * CSTR + (x3 + j3) * RSTR + 3 + x4;
                const float* r1 = r0 + RSTR;
                u64 vd0[4], vd1[4];
#pragma unroll
                for (int t = 0; t < 4; ++t) {
                    float a = r0[t]; vd0[t] = pack2(a, a);
                    float c2 = r1[t]; vd1[t] = pack2(c2, c2);
                }
                const float* wb = wsm + (ci * 81 + j1 * 27 + j2 * 9 + j3 * 3) * CP2;
#pragma unroll
                for (int j4 = 0; j4 < 3; ++j4) {
#pragma unroll
                    for (int cp = 0; cp < COP; ++cp) {
                        u64 wp = *reinterpret_cast<const u64*>(wb + j4 * CP2 + cp * 2);
                        fma2(acc[cp][0], wp, vd0[j4]);       // (x3,   x4)
                        fma2(acc[cp][1], wp, vd0[j4 + 1]);   // (x3,   x4+1)
                        fma2(acc[cp][2], wp, vd1[j4]);       // (x3+1, x4)
                        fma2(acc[cp][3], wp, vd1[j4 + 1]);   // (x3+1, x4+1)
                    }
                }
            }
        }
    }

    // epilogue: 2x2 outputs per channel -> 2 float2 stores per co
    int pos0 = x3 * 24 + x4;
#pragma unroll
    for (int cp = 0; cp < COP; ++cp) {
        int co0 = 2 * cp, co1 = co0 + 1;
        float2 q0 = unpack2(acc[cp][0]);   // (co0,co1) @ (x3,x4)
        float2 q1 = unpack2(acc[cp][1]);   // (co0,co1) @ (x3,x4+1)
        float2 q2 = unpack2(acc[cp][2]);   // (co0,co1) @ (x3+1,x4)
        float2 q3 = unpack2(acc[cp][3]);   // (co0,co1) @ (x3+1,x4+1)
        float b0 = bias[co0];
        size_t base0 = ((((size_t)b * COUT + co0) * 24 + x1) * 24 + x2) * POOL_P + pos0;
        *(float2*)(out + base0)      = make_float2(fmaxf(q0.x + b0, 0.f), fmaxf(q1.x + b0, 0.f));
        *(float2*)(out + base0 + 24) = make_float2(fmaxf(q2.x + b0, 0.f), fmaxf(q3.x + b0, 0.f));
        if (co1 < COUT) {
            float b1 = bias[co1];
            size_t base1 = ((((size_t)b * COUT + co1) * 24 + x1) * 24 + x2) * POOL_P + pos0;
            *(float2*)(out + base1)      = make_float2(fmaxf(q0.y + b1, 0.f), fmaxf(q1.y + b1, 0.f));
            *(float2*)(out + base1 + 24) = make_float2(fmaxf(q2.y + b1, 0.f), fmaxf(q3.y + b1, 0.f));
        }
    }
}

// host-side smem mirror
static inline size_t conv_smem_bytes(int cin, int cout) {
    int cp2 = (cout + 1) & ~1;
    size_t wpad = ((size_t)cin * 81 * cp2 + 3) & ~(size_t)3;
    return (wpad + 2 * (size_t)cin * CSTR) * 4;
}

// ---------------------------------------------------------------------------
// Launch
// ---------------------------------------------------------------------------
extern "C" void kernel_launch(void* const* d_in, const int* in_sizes, int n_in,
                              void* d_out, int out_size) {
    const float* fA = (const float*)d_in[0];
    const float* fB = (const float*)d_in[1];
    const float* w1 = (const float*)d_in[2];
    const float* b1 = (const float*)d_in[3];
    const float* w2 = (const float*)d_in[4];
    const float* b2 = (const float*)d_in[5];
    const float* w3 = (const float*)d_in[6];
    const float* b3 = (const float*)d_in[7];
    float* out = (float*)d_out;

    float *gA, *gB, *invA, *invB, *cpool, *x1b, *x2b, *amax, *bmax;
    cudaGetSymbolAddress((void**)&gA, g_A);
    cudaGetSymbolAddress((void**)&gB, g_B);
    cudaGetSymbolAddress((void**)&invA, g_invnA);
    cudaGetSymbolAddress((void**)&invB, g_invnB);
    cudaGetSymbolAddress((void**)&cpool, g_cpool);
    cudaGetSymbolAddress((void**)&x1b, g_x1);
    cudaGetSymbolAddress((void**)&x2b, g_x2);
    cudaGetSymbolAddress((void**)&amax, g_amax);
    cudaGetSymbolAddress((void**)&bmax, g_bmax);

    size_t sm1 = conv_smem_bytes(1, 10);    // ~10.7 KB
    size_t sm2 = conv_smem_bytes(10, 10);   // ~107.3 KB
    size_t sm3 = conv_smem_bytes(10, 1);    // ~81.4 KB
    size_t smg = 3 * 2 * STAGE_FLOATS * 4;  // 96 KB (3-stage)

    cudaFuncSetAttribute(gemm_pool_kernel, cudaFuncAttributeMaxDynamicSharedMemorySize, (int)smg);
    cudaFuncSetAttribute(conv4d_v4_kernel<10, 10>, cudaFuncAttributeMaxDynamicSharedMemorySize, (int)sm2);
    cudaFuncSetAttribute(conv4d_v4_kernel<10, 1>, cudaFuncAttributeMaxDynamicSharedMemorySize, (int)sm3);

    // 1) inverse norms
    invnorm_kernel<<<(2 * BATCH * HW) / 256, 256>>>(fA, fB);

    // 2) transpose + normalize + tf32 round into fragment-ordered layouts
    dim3 tgrid(72, 32, BATCH);
    transnorm_kernel<0><<<tgrid, 256>>>(fA, invA, gA);
    transnorm_kernel<1><<<tgrid, 256>>>(fB, invB, gB);

    // 3) TF32 GEMM + pool + relu/L2
    gemm_pool_kernel<<<dim3(18, 18, BATCH), 256, smg>>>(gA, gB, cpool);

    // 4) mutual matching #1 (in place)
    rowmax_kernel<<<dim3(POOL_P, BATCH), 64>>>(cpool, amax);
    colmax_kernel<<<dim3(POOL_P / 64, BATCH), 64>>>(cpool, bmax);
    mm_kernel<<<(POS_TOTAL + 255) / 256, 256>>>(cpool, amax, bmax, cpool);

    // 5) neighbourhood consensus convs (FFMA2 v4, 2x2 tiles)
    dim3 cgrid(12, 24, BATCH);
    conv4d_v4_kernel<1, 10><<<cgrid, 288, sm1>>>(cpool, w1, b1, x1b);
    conv4d_v4_kernel<10, 10><<<cgrid, 288, sm2>>>(x1b, w2, b2, x2b);
    conv4d_v4_kernel<10, 1><<<cgrid, 288, sm3>>>(x2b, w3, b3, cpool);

    // 6) mutual matching #2 -> output
    rowmax_kernel<<<dim3(POOL_P, BATCH), 64>>>(cpool, amax);
    colmax_kernel<<<dim3(POOL_P / 64, BATCH), 64>>>(cpool, bmax);
    mm_kernel<<<(POS_TOTAL + 255) / 256, 256>>>(cpool, amax, bmax, out);

    (void)in_sizes; (void)n_in; (void)out_size;
}

// round 8
// speedup vs baseline: 2.3204x; 1.0254x over previous
#include <cuda_runtime.h>
#include <cuda_bf16.h>

// ---------------------------------------------------------------------------
// Problem constants
// ---------------------------------------------------------------------------
#define BATCH 8
#define CHANNELS 1024
#define HW 2304           // 48*48
#define POOL_P 576        // 24*24
#define POS_TOTAL (BATCH*POOL_P*POOL_P)   // 2,654,208
#define EPS_L2 1e-6f
#define EPS_MM 1e-5f

typedef unsigned long long u64;

// ---------------------------------------------------------------------------
// Scratch (device globals; no allocation allowed)
// ---------------------------------------------------------------------------
__device__ float g_A[BATCH * HW * CHANNELS];
__device__ float g_B[BATCH * HW * CHANNELS];
__device__ float g_invnA[BATCH * HW];
__device__ float g_invnB[BATCH * HW];
__device__ float g_cpool[POS_TOTAL];
__device__ float g_x1[BATCH * 10 * POOL_P * POOL_P];
__device__ float g_x2[BATCH * 10 * POOL_P * POOL_P];
__device__ float g_amax[BATCH * POOL_P];      // reciprocals 1/(max+eps)
__device__ float g_bmax[BATCH * POOL_P];

// ---------------------------------------------------------------------------
// Helpers
// ---------------------------------------------------------------------------
__device__ __forceinline__ unsigned smem_u32(const void* p) {
    return (unsigned)__cvta_generic_to_shared(p);
}
__device__ __forceinline__ u64 pack2(float a, float b) {
    u64 r; asm("mov.b64 %0, {%1, %2};" : "=l"(r) : "f"(a), "f"(b)); return r;
}
__device__ __forceinline__ void fma2(u64& d, u64 a, u64 b) {
    asm("fma.rn.f32x2 %0, %1, %2, %0;" : "+l"(d) : "l"(a), "l"(b));
}
__device__ __forceinline__ float2 unpack2(u64 v) {
    float2 r; asm("mov.b64 {%0, %1}, %2;" : "=f"(r.x), "=f"(r.y) : "l"(v)); return r;
}
__device__ __forceinline__ float tf32r(float v) {
    unsigned t; asm("cvt.rna.tf32.f32 %0, %1;" : "=r"(t) : "f"(v));
    return __uint_as_float(t);
}

// ---------------------------------------------------------------------------
// 1) inverse L2 norm per (b, hw)
// ---------------------------------------------------------------------------
__global__ void invnorm_kernel(const float* __restrict__ A, const float* __restrict__ B) {
    int t = blockIdx.x * blockDim.x + threadIdx.x;
    if (t >= 2 * BATCH * HW) return;
    const float* f = (t < BATCH * HW) ? A : B;
    float* o = (t < BATCH * HW) ? g_invnA : g_invnB;
    int idx = t % (BATCH * HW);
    int b = idx / HW, hw = idx % HW;
    const float* p = f + (size_t)b * CHANNELS * HW + hw;
    float s = 0.f;
#pragma unroll 16
    for (int c = 0; c < CHANNELS; ++c) {
        float v = p[(size_t)c * HW];
        s = fmaf(v, v, s);
    }
    o[idx] = rsqrtf(s + EPS_L2);
}

// ---------------------------------------------------------------------------
// 2) transpose + normalize + tf32-round into MMA-fragment layout
//    A: [b][rowblk 18][ktile 128][mtile 8][lane 32][4]
//    B: [b][colblk 18][ktile 128][ntile 16][lane 32][2]
// ---------------------------------------------------------------------------
template <int MODE>
__global__ __launch_bounds__(256) void transnorm_kernel(
    const float* __restrict__ f, const float* __restrict__ invn,
    float* __restrict__ out) {
    __shared__ float sm[32][33];
    int b = blockIdx.z;
    int pb = blockIdx.x;
    int c0 = blockIdx.y * 32;
    int g0 = pb * 8;
    int hbase = (g0 / 24) * 2;
    int wbase = (g0 % 24) * 2;
    int tid = threadIdx.x;

    for (int idx = tid; idx < 1024; idx += 256) {
        int ci = idx >> 5, pos = idx & 31;
        int hh = pos >> 4, ww = pos & 15;
        int hw = (hbase + hh) * 48 + wbase + ww;
        float v = f[((size_t)b * CHANNELS + c0 + ci) * HW + hw] * invn[b * HW + hw];
        int p_in = ((ww >> 1) << 2) | (hh << 1) | (ww & 1);
        sm[p_in][ci] = tf32r(v);
    }
    __syncthreads();

    int p0 = pb * 32;
    if (MODE == 0) {
        int mt = tid >> 7, kt = (tid >> 5) & 3, lane = tid & 31;
        int rowin = lane >> 2, colin = lane & 3;
        float4 v;
        v.x = sm[mt * 16 + rowin][kt * 8 + colin];
        v.y = sm[mt * 16 + rowin + 8][kt * 8 + colin];
        v.z = sm[mt * 16 + rowin][kt * 8 + colin + 4];
        v.w = sm[mt * 16 + rowin + 8][kt * 8 + colin + 4];
        int rowblk = p0 >> 7;
        int mtile_g = ((p0 >> 4) & 7) + mt;
        int ktile_g = (c0 >> 3) + kt;
        size_t off = ((((size_t)b * 18 + rowblk) * 128 + ktile_g) * 8 + mtile_g) * 128
                     + lane * 4;
        *(float4*)(out + off) = v;
    } else {
        int colblk = p0 >> 7;
#pragma unroll
        for (int i = 0; i < 2; ++i) {
            int id = tid + i * 256;
            int nt = id >> 7, kt = (id >> 5) & 3, lane = id & 31;
            int rowin = lane >> 2, colin = lane & 3;
            float2 v;
            v.x = sm[nt * 8 + rowin][kt * 8 + colin];
            v.y = sm[nt * 8 + rowin][kt * 8 + colin + 4];
            int ntile_g = ((p0 >> 3) & 15) + nt;
            int ktile_g = (c0 >> 3) + kt;
            size_t off = ((((size_t)b * 18 + colblk) * 128 + ktile_g) * 16 + ntile_g) * 64
                         + lane * 2;
            *(float2*)(out + off) = v;
        }
    }
}

// ---------------------------------------------------------------------------
// 3) batched TF32 GEMM + fused 4x4 max-pool + relu/L2.
//    v2: 128 threads, 4 warps, 64x64 warp tiles -> 1.0 crossbar-wf per mma
//    (was 1.5) to lift the smem-crossbar bound. 3-stage cp.async.
// ---------------------------------------------------------------------------
#define STAGE_FLOATS 4096   // 4 ktiles * 1024 floats

__global__ __launch_bounds__(128) void gemm_pool_kernel(
    const float* __restrict__ A, const float* __restrict__ B,
    float* __restrict__ out) {
    extern __shared__ char smem_raw[];
    float* As = (float*)smem_raw;            // [3][4096]
    float* Bs = As + 3 * STAGE_FLOATS;       // [3][4096]
    float* Cs = (float*)smem_raw;            // reused: [128][132]

    int b = blockIdx.z;
    const float* Ag = A + (size_t)b * HW * CHANNELS + (size_t)blockIdx.y * 128 * 1024;
    const float* Bg = B + (size_t)b * HW * CHANNELS + (size_t)blockIdx.x * 128 * 1024;

    int tid = threadIdx.x, lane = tid & 31, wid = tid >> 5;
    int wm = wid >> 1, wn = wid & 1;   // 2x2 warp grid, warp tile 64x64

    float acc[4][8][4];
#pragma unroll
    for (int i = 0; i < 4; ++i)
#pragma unroll
        for (int j = 0; j < 8; ++j)
#pragma unroll
            for (int k = 0; k < 4; ++k) acc[i][j][k] = 0.f;

    auto load_stage = [&](int s, int kt) {
        const float* ga = Ag + (size_t)kt * STAGE_FLOATS;
        const float* gb = Bg + (size_t)kt * STAGE_FLOATS;
#pragma unroll
        for (int i = 0; i < 8; ++i) {
            int idx = tid + i * 128;   // float4 chunk 0..1023
            unsigned sa = smem_u32(As + s * STAGE_FLOATS + idx * 4);
            asm volatile("cp.async.cg.shared.global [%0], [%1], 16;\n" :: "r"(sa), "l"(ga + idx * 4));
            unsigned sb = smem_u32(Bs + s * STAGE_FLOATS + idx * 4);
            asm volatile("cp.async.cg.shared.global [%0], [%1], 16;\n" :: "r"(sb), "l"(gb + idx * 4));
        }
        asm volatile("cp.async.commit_group;\n");
    };

    const int KT = CHANNELS / 32;   // 32 k-iterations
    load_stage(0, 0);
    load_stage(1, 1);
    for (int kt = 0; kt < KT; ++kt) {
        if (kt + 2 < KT) {
            asm volatile("cp.async.wait_group 1;\n");
        } else {
            asm volatile("cp.async.wait_group 0;\n");
        }
        __syncthreads();
        if (kt + 2 < KT) load_stage((kt + 2) % 3, kt + 2);
        int cur = kt % 3;
        const float* Ab = As + cur * STAGE_FLOATS;
        const float* Bb = Bs + cur * STAGE_FLOATS;
#pragma unroll
        for (int kk = 0; kk < 4; ++kk) {
            uint2 bf[8];
#pragma unroll
            for (int ni = 0; ni < 8; ++ni)
                bf[ni] = *(const uint2*)(Bb + ((kk * 16 + wn * 8 + ni) * 32 + lane) * 2);
#pragma unroll
            for (int mi = 0; mi < 4; ++mi) {
                uint4 af = *(const uint4*)(Ab + ((kk * 8 + wm * 4 + mi) * 32 + lane) * 4);
#pragma unroll
                for (int ni = 0; ni < 8; ++ni) {
                    asm volatile(
                        "mma.sync.aligned.m16n8k8.row.col.f32.tf32.tf32.f32 "
                        "{%0,%1,%2,%3}, {%4,%5,%6,%7}, {%8,%9}, {%0,%1,%2,%3};\n"
                        : "+f"(acc[mi][ni][0]), "+f"(acc[mi][ni][1]),
                          "+f"(acc[mi][ni][2]), "+f"(acc[mi][ni][3])
                        : "r"(af.x), "r"(af.y), "r"(af.z), "r"(af.w),
                          "r"(bf[ni].x), "r"(bf[ni].y));
                }
            }
        }
    }
    __syncthreads();   // operand smem free; reuse as Cs

#pragma unroll
    for (int mi = 0; mi < 4; ++mi) {
#pragma unroll
        for (int ni = 0; ni < 8; ++ni) {
            int r0 = wm * 64 + mi * 16 + (lane >> 2);
            int c0 = wn * 64 + ni * 8 + (lane & 3) * 2;
            Cs[r0 * 132 + c0]           = acc[mi][ni][0];
            Cs[r0 * 132 + c0 + 1]       = acc[mi][ni][1];
            Cs[(r0 + 8) * 132 + c0]     = acc[mi][ni][2];
            Cs[(r0 + 8) * 132 + c0 + 1] = acc[mi][ni][3];
        }
    }
    __syncthreads();

#pragma unroll
    for (int o = 0; o < 8; ++o) {
        int idx = tid * 8 + o;
        int pp = idx >> 5, qq = idx & 31;
        float m = -1e30f;
#pragma unroll
        for (int i = 0; i < 4; ++i)
#pragma unroll
            for (int j = 0; j < 4; ++j)
                m = fmaxf(m, Cs[(pp * 4 + i) * 132 + qq * 4 + j]);
        m = fmaxf(m, 0.f);
        float v = m * rsqrtf(m * m + EPS_L2);
        out[((size_t)b * POOL_P + blockIdx.y * 32 + pp) * POOL_P + blockIdx.x * 32 + qq] = v;
    }
}

// ---------------------------------------------------------------------------
// 4) row / col maxes -> reciprocals 1/(max+eps)
// ---------------------------------------------------------------------------
__global__ void rowmax_kernel(const float* __restrict__ X, float* __restrict__ amax) {
    int row = blockIdx.x, b = blockIdx.y;
    const float* p = X + ((size_t)b * POOL_P + row) * POOL_P;
    float m = 0.f;
    for (int q = threadIdx.x; q < POOL_P; q += 64) m = fmaxf(m, p[q]);
    __shared__ float red[64];
    red[threadIdx.x] = m;
    __syncthreads();
    if (threadIdx.x < 32) {
        m = fmaxf(red[threadIdx.x], red[threadIdx.x + 32]);
#pragma unroll
        for (int s = 16; s; s >>= 1) m = fmaxf(m, __shfl_down_sync(0xffffffffu, m, s));
        if (threadIdx.x == 0) amax[b * POOL_P + row] = 1.0f / (m + EPS_MM);
    }
}

__global__ void colmax_kernel(const float* __restrict__ X, float* __restrict__ bmax) {
    int q = blockIdx.x * 64 + threadIdx.x;
    int b = blockIdx.y;
    const float* p = X + (size_t)b * POOL_P * POOL_P + q;
    float m = 0.f;
#pragma unroll 8
    for (int r = 0; r < POOL_P; ++r) m = fmaxf(m, p[(size_t)r * POOL_P]);
    bmax[b * POOL_P + q] = 1.0f / (m + EPS_MM);
}

// ---------------------------------------------------------------------------
// 5) mutual matching: out = c * (c*ainv[p]) * (c*binv[q])
// ---------------------------------------------------------------------------
__global__ void mm_kernel(const float* __restrict__ X, const float* __restrict__ am,
                          const float* __restrict__ bm, float* __restrict__ O) {
    int i = blockIdx.x * blockDim.x + threadIdx.x;
    if (i >= POS_TOTAL) return;
    int q = i % POOL_P;
    int pr = (i / POOL_P) % POOL_P;
    int b = i / (POOL_P * POOL_P);
    float c = X[i];
    float r = c * am[b * POOL_P + pr];
    float s = c * bm[b * POOL_P + q];
    O[i] = c * r * s;
}

// ---------------------------------------------------------------------------
// 6) Conv4d FFMA2 v4 (COUT>=2): 288 thr = 2 x2-planes x 144; 2x2 (x3,x4)
//    output tile per thread, weight-pair packing.
// ---------------------------------------------------------------------------
#define RSTR 36              // plane row stride (floats)
#define CSTR (26 * RSTR)     // 936 floats per channel

template <int CIN, int COUT>
__global__ __launch_bounds__(288) void conv4d_v4_kernel(
    const float* __restrict__ in, const float* __restrict__ w,
    const float* __restrict__ bias, float* __restrict__ out) {
    constexpr int CP2 = (COUT + 1) & ~1;
    constexpr int COP = CP2 / 2;
    constexpr int WPAD = (CIN * 81 * CP2 + 3) & ~3;
    constexpr int PLN = CIN * CSTR;
    extern __shared__ float sm[];
    float* wsm = sm;
    float* pl = sm + WPAD;

    int tid = threadIdx.x;
    int b = blockIdx.z, x1 = blockIdx.y, bx = blockIdx.x;
    int half = tid / 144, u = tid % 144;
    int x3 = 2 * (u / 12), x4 = 2 * (u % 12);
    int x2 = bx * 2 + half;

    for (int i = tid; i < CIN * 81 * CP2; i += 288) {
        int co = i % CP2;
        int rest = i / CP2;
        int ci = rest / 81, tap = rest % 81;
        wsm[i] = (co < COUT) ? w[(co * CIN + ci) * 81 + tap] : 0.f;
    }
    for (int i = tid; i < 2 * CIN * 26; i += 288) {
        int h = i / (CIN * 26), r = i % (CIN * 26);
        int ci = r / 26, rr = r % 26;
        float* rowp = pl + h * PLN + ci * CSTR + rr * RSTR;
        if (rr == 0 || rr == 25) {
            for (int c = 3; c <= 28; ++c) rowp[c] = 0.f;
        } else {
            rowp[3] = 0.f; rowp[28] = 0.f;
        }
    }

    u64 acc[COP][4];
#pragma unroll
    for (int cp = 0; cp < COP; ++cp)
#pragma unroll
        for (int o = 0; o < 4; ++o) acc[cp][o] = 0ull;

    for (int g = 0; g < 9; ++g) {
        int j1 = g / 3, j2 = g % 3;
        int y1 = x1 + j1 - 1;
        bool v1 = (unsigned)y1 < 24u;
        __syncthreads();
        for (int t = tid; t < 2 * CIN * 24; t += 288) {
            int h = t / (CIN * 24), r = t % (CIN * 24);
            int ci = r / 24, rr = 1 + r % 24;
            int y2 = bx * 2 + h + j2 - 1;
            float* dst = pl + h * PLN + ci * CSTR + rr * RSTR + 4;
            if (v1 && (unsigned)y2 < 24u) {
                const float* src = in + ((((size_t)b * CIN + ci) * 24 + y1) * 24 + y2) * POOL_P
                                      + (rr - 1) * 24;
#pragma unroll
                for (int c = 0; c < 6; ++c)
                    *(float4*)(dst + c * 4) = *(const float4*)(src + c * 4);
            } else {
                float4 z = make_float4(0.f, 0.f, 0.f, 0.f);
#pragma unroll
                for (int c = 0; c < 6; ++c) *(float4*)(dst + c * 4) = z;
            }
        }
        __syncthreads();

        const float* base = pl + half * PLN;
        for (int ci = 0; ci < CIN; ++ci) {
#pragma unroll
            for (int j3 = 0; j3 < 3; ++j3) {
                const float* r0 = base + ci * CSTR + (x3 + j3) * RSTR + 3 + x4;
                const float* r1 = r0 + RSTR;
                u64 vd0[4], vd1[4];
#pragma unroll
                for (int t = 0; t < 4; ++t) {
                    float a = r0[t]; vd0[t] = pack2(a, a);
                    float c2 = r1[t]; vd1[t] = pack2(c2, c2);
                }
                const float* wb = wsm + (ci * 81 + j1 * 27 + j2 * 9 + j3 * 3) * CP2;
#pragma unroll
                for (int j4 = 0; j4 < 3; ++j4) {
#pragma unroll
                    for (int cp = 0; cp < COP; ++cp) {
                        u64 wp = *reinterpret_cast<const u64*>(wb + j4 * CP2 + cp * 2);
                        fma2(acc[cp][0], wp, vd0[j4]);
                        fma2(acc[cp][1], wp, vd0[j4 + 1]);
                        fma2(acc[cp][2], wp, vd1[j4]);
                        fma2(acc[cp][3], wp, vd1[j4 + 1]);
                    }
                }
            }
        }
    }

    int pos0 = x3 * 24 + x4;
#pragma unroll
    for (int cp = 0; cp < COP; ++cp) {
        int co0 = 2 * cp, co1 = co0 + 1;
        float2 q0 = unpack2(acc[cp][0]);
        float2 q1 = unpack2(acc[cp][1]);
        float2 q2 = unpack2(acc[cp][2]);
        float2 q3 = unpack2(acc[cp][3]);
        float b0 = bias[co0];
        size_t base0 = ((((size_t)b * COUT + co0) * 24 + x1) * 24 + x2) * POOL_P + pos0;
        *(float2*)(out + base0)      = make_float2(fmaxf(q0.x + b0, 0.f), fmaxf(q1.x + b0, 0.f));
        *(float2*)(out + base0 + 24) = make_float2(fmaxf(q2.x + b0, 0.f), fmaxf(q3.x + b0, 0.f));
        if (co1 < COUT) {
            float b1 = bias[co1];
            size_t base1 = ((((size_t)b * COUT + co1) * 24 + x1) * 24 + x2) * POOL_P + pos0;
            *(float2*)(out + base1)      = make_float2(fmaxf(q0.y + b1, 0.f), fmaxf(q1.y + b1, 0.f));
            *(float2*)(out + base1 + 24) = make_float2(fmaxf(q2.y + b1, 0.f), fmaxf(q3.y + b1, 0.f));
        }
    }
}

// ---------------------------------------------------------------------------
// 6b) Conv4d COUT=1 specialization: pack the two OUTPUT ROWS into one f32x2
//     (weights duplicated in smem as (w,w) u64) -> zero padded-lane waste.
// ---------------------------------------------------------------------------
template <int CIN>
__global__ __launch_bounds__(288) void conv4d_c1_kernel(
    const float* __restrict__ in, const float* __restrict__ w,
    const float* __restrict__ bias, float* __restrict__ out) {
    constexpr int WPAD = (2 * CIN * 81 + 3) & ~3;   // duplicated weights (u64 each)
    constexpr int PLN = CIN * CSTR;
    extern __shared__ float sm[];
    float* wsm = sm;                  // [CIN*81] as (w,w) float pairs
    float* pl = sm + WPAD;

    int tid = threadIdx.x;
    int b = blockIdx.z, x1 = blockIdx.y, bx = blockIdx.x;
    int half = tid / 144, u = tid % 144;
    int x3 = 2 * (u / 12), x4 = 2 * (u % 12);
    int x2 = bx * 2 + half;

    for (int i = tid; i < CIN * 81; i += 288) {
        float v = w[i];               // w layout (1, CIN, 81): co=0
        wsm[2 * i] = v; wsm[2 * i + 1] = v;
    }
    for (int i = tid; i < 2 * CIN * 26; i += 288) {
        int h = i / (CIN * 26), r = i % (CIN * 26);
        int ci = r / 26, rr = r % 26;
        float* rowp = pl + h * PLN + ci * CSTR + rr * RSTR;
        if (rr == 0 || rr == 25) {
            for (int c = 3; c <= 28; ++c) rowp[c] = 0.f;
        } else {
            rowp[3] = 0.f; rowp[28] = 0.f;
        }
    }

    u64 acc[2] = {0ull, 0ull};        // col c: (row x3, row x3+1)

    for (int g = 0; g < 9; ++g) {
        int j1 = g / 3, j2 = g % 3;
        int y1 = x1 + j1 - 1;
        bool v1 = (unsigned)y1 < 24u;
        __syncthreads();
        for (int t = tid; t < 2 * CIN * 24; t += 288) {
            int h = t / (CIN * 24), r = t % (CIN * 24);
            int ci = r / 24, rr = 1 + r % 24;
            int y2 = bx * 2 + h + j2 - 1;
            float* dst = pl + h * PLN + ci * CSTR + rr * RSTR + 4;
            if (v1 && (unsigned)y2 < 24u) {
                const float* src = in + ((((size_t)b * CIN + ci) * 24 + y1) * 24 + y2) * POOL_P
                                      + (rr - 1) * 24;
#pragma unroll
                for (int c = 0; c < 6; ++c)
                    *(float4*)(dst + c * 4) = *(const float4*)(src + c * 4);
            } else {
                float4 z = make_float4(0.f, 0.f, 0.f, 0.f);
#pragma unroll
                for (int c = 0; c < 6; ++c) *(float4*)(dst + c * 4) = z;
            }
        }
        __syncthreads();

        const float* base = pl + half * PLN;
        for (int ci = 0; ci < CIN; ++ci) {
#pragma unroll
            for (int j3 = 0; j3 < 3; ++j3) {
                const float* r0 = base + ci * CSTR + (x3 + j3) * RSTR + 3 + x4;
                const float* r1 = r0 + RSTR;
                u64 vd[4];
#pragma unroll
                for (int t = 0; t < 4; ++t) vd[t] = pack2(r0[t], r1[t]);
                const u64* wb = reinterpret_cast<const u64*>(
                    wsm + 2 * (ci * 81 + j1 * 27 + j2 * 9 + j3 * 3));
#pragma unroll
                for (int j4 = 0; j4 < 3; ++j4) {
                    u64 wp = wb[j4];
                    fma2(acc[0], wp, vd[j4]);
                    fma2(acc[1], wp, vd[j4 + 1]);
                }
            }
        }
    }

    float b0 = bias[0];
    float2 c0 = unpack2(acc[0]);      // (row0, row1) @ x4
    float2 c1 = unpack2(acc[1]);      // (row0, row1) @ x4+1
    size_t base0 = (((size_t)b * 24 + x1) * 24 + x2) * POOL_P + x3 * 24 + x4;
    *(float2*)(out + base0)      = make_float2(fmaxf(c0.x + b0, 0.f), fmaxf(c1.x + b0, 0.f));
    *(float2*)(out + base0 + 24) = make_float2(fmaxf(c0.y + b0, 0.f), fmaxf(c1.y + b0, 0.f));
}

// host-side smem mirrors
static inline size_t conv_smem_bytes(int cin, int cout) {
    int cp2 = (cout + 1) & ~1;
    size_t wpad = ((size_t)cin * 81 * cp2 + 3) & ~(size_t)3;
    return (wpad + 2 * (size_t)cin * CSTR) * 4;
}
static inline size_t conv_c1_smem_bytes(int cin) {
    size_t wpad = (2 * (size_t)cin * 81 + 3) & ~(size_t)3;
    return (wpad + 2 * (size_t)cin * CSTR) * 4;
}

// ---------------------------------------------------------------------------
// Launch
// ---------------------------------------------------------------------------
extern "C" void kernel_launch(void* const* d_in, const int* in_sizes, int n_in,
                              void* d_out, int out_size) {
    const float* fA = (const float*)d_in[0];
    const float* fB = (const float*)d_in[1];
    const float* w1 = (const float*)d_in[2];
    const float* b1 = (const float*)d_in[3];
    const float* w2 = (const float*)d_in[4];
    const float* b2 = (const float*)d_in[5];
    const float* w3 = (const float*)d_in[6];
    const float* b3 = (const float*)d_in[7];
    float* out = (float*)d_out;

    float *gA, *gB, *invA, *invB, *cpool, *x1b, *x2b, *amax, *bmax;
    cudaGetSymbolAddress((void**)&gA, g_A);
    cudaGetSymbolAddress((void**)&gB, g_B);
    cudaGetSymbolAddress((void**)&invA, g_invnA);
    cudaGetSymbolAddress((void**)&invB, g_invnB);
    cudaGetSymbolAddress((void**)&cpool, g_cpool);
    cudaGetSymbolAddress((void**)&x1b, g_x1);
    cudaGetSymbolAddress((void**)&x2b, g_x2);
    cudaGetSymbolAddress((void**)&amax, g_amax);
    cudaGetSymbolAddress((void**)&bmax, g_bmax);

    size_t sm1 = conv_smem_bytes(1, 10);
    size_t sm2 = conv_smem_bytes(10, 10);
    size_t sm3 = conv_c1_smem_bytes(10);
    size_t smg = 3 * 2 * STAGE_FLOATS * 4;   // 96 KB

    cudaFuncSetAttribute(gemm_pool_kernel, cudaFuncAttributeMaxDynamicSharedMemorySize, (int)smg);
    cudaFuncSetAttribute(conv4d_v4_kernel<10, 10>, cudaFuncAttributeMaxDynamicSharedMemorySize, (int)sm2);
    cudaFuncSetAttribute(conv4d_c1_kernel<10>, cudaFuncAttributeMaxDynamicSharedMemorySize, (int)sm3);

    // 1) inverse norms
    invnorm_kernel<<<(2 * BATCH * HW) / 256, 256>>>(fA, fB);

    // 2) transpose + normalize + tf32 round into fragment-ordered layouts
    dim3 tgrid(72, 32, BATCH);
    transnorm_kernel<0><<<tgrid, 256>>>(fA, invA, gA);
    transnorm_kernel<1><<<tgrid, 256>>>(fB, invB, gB);

    // 3) TF32 GEMM (64x64 warp tiles) + pool + relu/L2
    gemm_pool_kernel<<<dim3(18, 18, BATCH), 128, smg>>>(gA, gB, cpool);

    // 4) mutual matching #1 (in place)
    rowmax_kernel<<<dim3(POOL_P, BATCH), 64>>>(cpool, amax);
    colmax_kernel<<<dim3(POOL_P / 64, BATCH), 64>>>(cpool, bmax);
    mm_kernel<<<(POS_TOTAL + 255) / 256, 256>>>(cpool, amax, bmax, cpool);

    // 5) neighbourhood consensus convs
    dim3 cgrid(12, 24, BATCH);
    conv4d_v4_kernel<1, 10><<<cgrid, 288, sm1>>>(cpool, w1, b1, x1b);
    conv4d_v4_kernel<10, 10><<<cgrid, 288, sm2>>>(x1b, w2, b2, x2b);
    conv4d_c1_kernel<10><<<cgrid, 288, sm3>>>(x2b, w3, b3, cpool);

    // 6) mutual matching #2 -> output
    rowmax_kernel<<<dim3(POOL_P, BATCH), 64>>>(cpool, amax);
    colmax_kernel<<<dim3(POOL_P / 64, BATCH), 64>>>(cpool, bmax);
    mm_kernel<<<(POS_TOTAL + 255) / 256, 256>>>(cpool, amax, bmax, out);

    (void)in_sizes; (void)n_in; (void)out_size;
}